// round 1
// baseline (speedup 1.0000x reference)
#include <cuda_runtime.h>

#define THREADS 256
#define Q 6
#define DIM 1024
#define ROWS_PER_CHUNK 16   // 8 warps x 2 rows

__global__ __launch_bounds__(THREADS)
void ffq_kernel(const float* __restrict__ x,
                const float* __restrict__ w1,
                const float* __restrict__ b1,
                const float* __restrict__ theta,
                const float* __restrict__ w2,
                const float* __restrict__ b2,
                float* __restrict__ out,
                int n_rows)
{
    __shared__ float w1s[Q][DIM];                 // 24 KB
    __shared__ float qvs[ROWS_PER_CHUNK][8];      // q-values per chunk row (padded)

    const int tid  = threadIdx.x;
    const int wid  = tid >> 5;
    const int lane = tid & 31;

    // ---- Stage w1 into SMEM: 6144 floats = 1536 float4, 6 per thread ----
    {
        const float4* __restrict__ w1v  = (const float4*)w1;
        float4* w1sv = (float4*)&w1s[0][0];
        #pragma unroll
        for (int i = 0; i < 6; i++)
            w1sv[tid + i * THREADS] = w1v[tid + i * THREADS];
    }

    // ---- Per-thread constants ----
    float b1r[Q], ctr[Q];
    #pragma unroll
    for (int q = 0; q < Q; q++) {
        b1r[q] = __ldg(&b1[q]);
        ctr[q] = cosf(__ldg(&theta[q]));
    }

    // ---- Register-stationary w2 slice: thread t owns d = 4t..4t+3 ----
    const int d0 = tid * 4;
    float w2r[4][Q], b2r[4];
    #pragma unroll
    for (int j = 0; j < 4; j++) {
        b2r[j] = __ldg(&b2[d0 + j]);
        #pragma unroll
        for (int q = 0; q < Q; q++)
            w2r[j][q] = __ldg(&w2[(d0 + j) * Q + q]);
    }
    __syncthreads();

    const int n_chunks = n_rows / ROWS_PER_CHUNK;
    for (int c = blockIdx.x; c < n_chunks; c += gridDim.x) {
        const int base = c * ROWS_PER_CHUNK;

        // ================= Phase A: proj + quantum expvals =================
        // Warp `wid` handles rows base+2*wid and base+2*wid+1.
        {
            const int rA = base + wid * 2;
            const int rB = rA + 1;
            const float4* __restrict__ xA = (const float4*)(x + (size_t)rA * DIM);
            const float4* __restrict__ xB = (const float4*)(x + (size_t)rB * DIM);

            float sA[Q], sB[Q];
            #pragma unroll
            for (int q = 0; q < Q; q++) { sA[q] = 0.f; sB[q] = 0.f; }

            #pragma unroll
            for (int i = 0; i < 8; i++) {
                const int col = i * 32 + lane;        // float4 index: coalesced
                const float4 a = __ldcs(&xA[col]);
                const float4 b = __ldcs(&xB[col]);
                #pragma unroll
                for (int q = 0; q < Q; q++) {
                    const float4 w = *(const float4*)&w1s[q][col * 4];
                    sA[q] += a.x * w.x + a.y * w.y + a.z * w.z + a.w * w.w;
                    sB[q] += b.x * w.x + b.y * w.y + b.z * w.z + b.w * w.w;
                }
            }

            // Butterfly reduce 6 partial sums per row across the warp.
            #pragma unroll
            for (int off = 16; off > 0; off >>= 1) {
                #pragma unroll
                for (int q = 0; q < Q; q++) {
                    sA[q] += __shfl_xor_sync(0xffffffffu, sA[q], off);
                    sB[q] += __shfl_xor_sync(0xffffffffu, sB[q], off);
                }
            }

            if (lane == 0) {
                #pragma unroll
                for (int q = 0; q < Q; q++) {
                    qvs[wid * 2 + 0][q] = __cosf(sA[q] + b1r[q]) * ctr[q];
                    qvs[wid * 2 + 1][q] = __cosf(sB[q] + b1r[q]) * ctr[q];
                }
            }
        }
        __syncthreads();

        // ================= Phase B: out = relu(q @ w2^T + b2) =================
        #pragma unroll 4
        for (int r = 0; r < ROWS_PER_CHUNK; r++) {
            float a0 = b2r[0], a1 = b2r[1], a2 = b2r[2], a3 = b2r[3];
            #pragma unroll
            for (int q = 0; q < Q; q++) {
                const float qv = qvs[r][q];           // SMEM broadcast
                a0 += qv * w2r[0][q];
                a1 += qv * w2r[1][q];
                a2 += qv * w2r[2][q];
                a3 += qv * w2r[3][q];
            }
            float4 o;
            o.x = fmaxf(a0, 0.f);
            o.y = fmaxf(a1, 0.f);
            o.z = fmaxf(a2, 0.f);
            o.w = fmaxf(a3, 0.f);
            *(float4*)(out + (size_t)(base + r) * DIM + d0) = o;
        }
        __syncthreads();   // protect qvs before next chunk's phase A
    }
}

extern "C" void kernel_launch(void* const* d_in, const int* in_sizes, int n_in,
                              void* d_out, int out_size)
{
    const float* x     = (const float*)d_in[0];
    const float* w1    = (const float*)d_in[1];
    const float* b1    = (const float*)d_in[2];
    const float* theta = (const float*)d_in[3];
    const float* w2    = (const float*)d_in[4];
    const float* b2    = (const float*)d_in[5];
    float* out = (float*)d_out;

    const int n_rows = in_sizes[0] / DIM;   // 65536

    const int grid = 1184;                   // 148 SMs * 8, grid-stride over chunks
    ffq_kernel<<<grid, THREADS>>>(x, w1, b1, theta, w2, b2, out, n_rows);
}